// round 15
// baseline (speedup 1.0000x reference)
#include <cuda_runtime.h>
#include <cuda_bf16.h>
#include <math.h>
#include <stdint.h>

// ---------------------------------------------------------------------------
// T6Attention — round 15: 512-thread GEMM (16 warps, warp tile 32x32)
// B=2, S=2048, D_MODEL=1024, HEADS=16, DK=64, Q_RANK=6, RANK=2
// ---------------------------------------------------------------------------

#define BATCH     2
#define SEQ       2048
#define DMODEL    1024
#define HEADS     16
#define DK        64
#define QRANK     6
#define RANK      2
#define NTOK      (BATCH*SEQ)        // 4096
#define BH        (BATCH*HEADS)      // 32

// fp32 scratch offsets
#define OFF_AQ   0
#define SZ_AQ    (NTOK*HEADS*QRANK)
#define OFF_AK   (OFF_AQ+SZ_AQ)
#define SZ_AK    (NTOK*HEADS*RANK)
#define OFF_AV   (OFF_AK+SZ_AK)
#define SZ_AV    SZ_AK
#define OFF_BQ   (OFF_AV+SZ_AV)
#define SZ_BQ    (NTOK*QRANK*DK)
#define OFF_BK   (OFF_BQ+SZ_BQ)
#define SZ_BK    (NTOK*RANK*DK)
#define OFF_BV   (OFF_BK+SZ_BK)
#define SZ_BV    SZ_BK
#define SCRATCH_TOTAL (OFF_BV+SZ_BV)

__device__ float g_scratch[SCRATCH_TOTAL];
__device__ float2 g_rope[SEQ * 32];

// bf16 scratch offsets (elements)
#define TOKD          (NTOK*DMODEL)
#define BOFF_QHI      0
#define BOFF_QLO      (BOFF_QHI + TOKD)
#define BOFF_KHI      (BOFF_QLO + TOKD)
#define BOFF_KLO      (BOFF_KHI + TOKD)
#define BOFF_VHI      (BOFF_KLO + TOKD)
#define BOFF_VLO      (BOFF_VHI + TOKD)
#define BOFF_OAHI     (BOFF_VLO + TOKD)
#define BOFF_OALO     (BOFF_OAHI + TOKD)
#define BOFF_WBQ_HI   (BOFF_OALO + TOKD)
#define BOFF_WBQ_LO   (BOFF_WBQ_HI + 384*1024)
#define BOFF_WBK_HI   (BOFF_WBQ_LO + 384*1024)
#define BOFF_WBK_LO   (BOFF_WBK_HI + 128*1024)
#define BOFF_WBV_HI   (BOFF_WBK_LO + 128*1024)
#define BOFF_WBV_LO   (BOFF_WBV_HI + 128*1024)
#define BOFF_WO_HI    (BOFF_WBV_LO + 128*1024)
#define BOFF_WO_LO    (BOFF_WO_HI + 1024*1024)
#define BOFF_WAQ_HI   (BOFF_WO_LO + 1024*1024)
#define BOFF_WAQ_LO   (BOFF_WAQ_HI + 128*1024)
#define BOFF_WAK_HI   (BOFF_WAQ_LO + 128*1024)
#define BOFF_WAK_LO   (BOFF_WAK_HI + 128*1024)
#define BOFF_WAV_HI   (BOFF_WAK_LO + 128*1024)
#define BOFF_WAV_LO   (BOFF_WAV_HI + 128*1024)
#define BOFF_FQHI     (BOFF_WAV_LO + 128*1024)
#define BOFF_FQLO     (BOFF_FQHI + TOKD)
#define BOFF_FKHI     (BOFF_FQLO + TOKD)
#define BOFF_FKLO     (BOFF_FKHI + TOKD)
#define BOFF_FVTHI    (BOFF_FKLO + TOKD)
#define BOFF_FVTLO    (BOFF_FVTHI + TOKD)
#define BF_TOTAL      (BOFF_FVTLO + TOKD)

__device__ __nv_bfloat16 g_bf[BF_TOTAL];

// ---------------------------------------------------------------------------
// helpers
// ---------------------------------------------------------------------------
__device__ __forceinline__ void mma16816(float* d,
                                         uint32_t a0, uint32_t a1, uint32_t a2, uint32_t a3,
                                         uint32_t b0, uint32_t b1)
{
    asm volatile(
        "mma.sync.aligned.m16n8k16.row.col.f32.bf16.bf16.f32 "
        "{%0,%1,%2,%3}, {%4,%5,%6,%7}, {%8,%9}, {%0,%1,%2,%3};"
        : "+f"(d[0]), "+f"(d[1]), "+f"(d[2]), "+f"(d[3])
        : "r"(a0), "r"(a1), "r"(a2), "r"(a3), "r"(b0), "r"(b1));
}

__device__ __forceinline__ void ldsm4(uint32_t& r0, uint32_t& r1,
                                      uint32_t& r2, uint32_t& r3, uint32_t addr)
{
    asm volatile("ldmatrix.sync.aligned.m8n8.x4.shared.b16 {%0,%1,%2,%3}, [%4];"
        : "=r"(r0), "=r"(r1), "=r"(r2), "=r"(r3) : "r"(addr));
}

__device__ __forceinline__ uint32_t packbf2(float a, float b) {
    __nv_bfloat162 t = __floats2bfloat162_rn(a, b);
    return *reinterpret_cast<uint32_t*>(&t);
}

__device__ __forceinline__ uint32_t smem_u32(const void* p) {
    return (uint32_t)__cvta_generic_to_shared(p);
}

#define CP_ASYNC16(dst_u32, src_ptr) \
    asm volatile("cp.async.cg.shared.global [%0], [%1], 16;" \
        :: "r"(dst_u32), "l"(src_ptr) : "memory")
#define CP_COMMIT() asm volatile("cp.async.commit_group;" ::: "memory")
#define CP_WAIT0()  asm volatile("cp.async.wait_group 0;" ::: "memory")
#define CP_WAIT1()  asm volatile("cp.async.wait_group 1;" ::: "memory")

// ---------------------------------------------------------------------------
// RoPE table
// ---------------------------------------------------------------------------
__global__ void rope_table_kernel()
{
    int idx = blockIdx.x * blockDim.x + threadIdx.x;
    if (idx >= SEQ * 32) return;
    int s = idx >> 5;
    int i = idx & 31;
    float inv_freq = powf(10000.0f, -(float)(2 * i) / 64.0f);
    float fr = (float)s * inv_freq;
    float sn, cs;
    sincosf(fr, &sn, &cs);
    g_rope[idx] = make_float2(cs, sn);
}

// ---------------------------------------------------------------------------
// batched hi/lo split for q,k,v
// ---------------------------------------------------------------------------
__global__ void split3_kernel(const float* __restrict__ x0, const float* __restrict__ x1,
                              const float* __restrict__ x2,
                              __nv_bfloat16* __restrict__ h0, __nv_bfloat16* __restrict__ l0p,
                              __nv_bfloat16* __restrict__ h1, __nv_bfloat16* __restrict__ l1p,
                              __nv_bfloat16* __restrict__ h2, __nv_bfloat16* __restrict__ l2p,
                              int n)
{
    const float* x = x0; __nv_bfloat16* hi = h0; __nv_bfloat16* lo = l0p;
    if (blockIdx.z == 1) { x = x1; hi = h1; lo = l1p; }
    else if (blockIdx.z == 2) { x = x2; hi = h2; lo = l2p; }
    int i = blockIdx.x * blockDim.x + threadIdx.x;
    if (i >= n) return;
    float v = x[i];
    __nv_bfloat16 h = __float2bfloat16(v);
    hi[i] = h;
    lo[i] = __float2bfloat16(v - __bfloat162float(h));
}

// ---------------------------------------------------------------------------
// batched transpose + split with zero padding: W[1024,N] -> hi/lo [Npad,1024]
// ---------------------------------------------------------------------------
struct TsCfg {
    const float* W;
    __nv_bfloat16* hi;
    __nv_bfloat16* lo;
    int N;
    int Npad;
};
struct TsCfg7 { TsCfg c[7]; };

__global__ void tsplit7_kernel(TsCfg7 p)
{
    TsCfg cfg = p.c[blockIdx.z];
    const int n0 = blockIdx.x * 32, k0 = blockIdx.y * 32;
    if (n0 >= cfg.Npad) return;
    const int tx = threadIdx.x, ty = threadIdx.y;

    if (n0 >= cfg.N) {
#pragma unroll
        for (int i = 0; i < 4; i++) {
            size_t o = (size_t)(n0 + ty + i * 8) * 1024 + k0 + tx;
            cfg.hi[o] = __float2bfloat16(0.f);
            cfg.lo[o] = __float2bfloat16(0.f);
        }
        return;
    }

    __shared__ float t[32][33];
#pragma unroll
    for (int i = 0; i < 4; i++)
        t[ty + i * 8][tx] = cfg.W[(size_t)(k0 + ty + i * 8) * cfg.N + n0 + tx];
    __syncthreads();
#pragma unroll
    for (int i = 0; i < 4; i++) {
        float v = t[tx][ty + i * 8];
        __nv_bfloat16 h = __float2bfloat16(v);
        size_t o = (size_t)(n0 + ty + i * 8) * 1024 + k0 + tx;
        cfg.hi[o] = h;
        cfg.lo[o] = __float2bfloat16(v - __bfloat162float(h));
    }
}

// ---------------------------------------------------------------------------
// HMMA GEMM, cp.async 2-stage pipelined (KTILE=64), ldmatrix loads,
// 512 threads = 16 warps (4M x 4N), warp tile 32x32.
// C[M,N] fp32 = A @ W via bf16 hi/lo (hihi+hilo+lohi). B pre-transposed
// [Npad,1024]. CTA 128x128 tile.
// ---------------------------------------------------------------------------
#define KPAD   72
#define GARR   (128 * KPAD * 2)           // 18432 B per array
#define GSTAGE (4 * GARR)                 // 73728 B

struct GemmCfg {
    const __nv_bfloat16 *Ahi, *Alo, *Bhi, *Blo;
    float* C;
    int N;
    int Npad;
};
struct GemmCfg6 { GemmCfg c[6]; };

__global__ __launch_bounds__(512) void tc_gemm_kernel(GemmCfg6 p)
{
    GemmCfg cfg = p.c[blockIdx.z];
    const int n0 = blockIdx.x * 128;
    if (n0 >= cfg.Npad) return;

    extern __shared__ char smem[];
    const uint32_t smem_base = smem_u32(smem);

    const int tid = threadIdx.x;
    const int wid = tid >> 5;
    const int lid = tid & 31;
    const int m0 = blockIdx.y * 128;
    const int wm = (wid & 3) * 32;       // 4 warps along M
    const int wn = (wid >> 2) * 32;      // 4 warps along N
    const int gr = lid >> 2;
    const int gc = (lid & 3) * 2;

    // ldmatrix lane geometry
    const int laneRowA  = (lid & 7) + ((lid >> 3) & 1) * 8;
    const int laneKoffA = (lid >> 4) * 8;
    const int laneRowB  = (lid & 7) + (lid >> 4) * 8;
    const int laneKoffB = ((lid >> 3) & 1) * 8;

    uint32_t offA[2], offB[2];
#pragma unroll
    for (int mf = 0; mf < 2; mf++)
        offA[mf] = (uint32_t)(((wm + mf * 16 + laneRowA) * KPAD + laneKoffA) * 2);
#pragma unroll
    for (int np = 0; np < 2; np++)
        offB[np] = (uint32_t)(((wn + np * 16 + laneRowB) * KPAD + laneKoffB) * 2);

    const char* pAhi = reinterpret_cast<const char*>(cfg.Ahi);
    const char* pAlo = reinterpret_cast<const char*>(cfg.Alo);
    const char* pBhi = reinterpret_cast<const char*>(cfg.Bhi);
    const char* pBlo = reinterpret_cast<const char*>(cfg.Blo);

    // G2S geometry: per array 1024 chunks, 2 per thread
    int cr[2], cc[2];
    uint32_t sdst[2];
#pragma unroll
    for (int i = 0; i < 2; i++) {
        int idx = tid + i * 512;
        cr[i] = idx >> 3;
        cc[i] = idx & 7;
        sdst[i] = (uint32_t)(cr[i] * (KPAD * 2) + cc[i] * 16);
    }

    auto issue = [&](int kc, int st) {
        uint32_t s0a = smem_base + st * GSTAGE;
#pragma unroll
        for (int i = 0; i < 2; i++) {
            size_t ga = 2 * ((size_t)(m0 + cr[i]) * 1024 + kc * 64 + cc[i] * 8);
            CP_ASYNC16(s0a + sdst[i],            pAhi + ga);
            CP_ASYNC16(s0a + GARR + sdst[i],     pAlo + ga);
            size_t gb = 2 * ((size_t)(n0 + cr[i]) * 1024 + kc * 64 + cc[i] * 8);
            CP_ASYNC16(s0a + 2 * GARR + sdst[i], pBhi + gb);
            CP_ASYNC16(s0a + 3 * GARR + sdst[i], pBlo + gb);
        }
        CP_COMMIT();
    };

    float acc[2][4][4];
#pragma unroll
    for (int mf = 0; mf < 2; mf++)
#pragma unroll
        for (int nf = 0; nf < 4; nf++)
#pragma unroll
            for (int e = 0; e < 4; e++) acc[mf][nf][e] = 0.f;

    issue(0, 0);

    for (int kc = 0; kc < 16; kc++) {
        const int st = kc & 1;
        if (kc + 1 < 16) { issue(kc + 1, st ^ 1); CP_WAIT1(); }
        else             { CP_WAIT0(); }
        __syncthreads();

        const uint32_t aHiBase = smem_base + st * GSTAGE;
        const uint32_t aLoBase = aHiBase + GARR;
        const uint32_t bHiBase = aHiBase + 2 * GARR;
        const uint32_t bLoBase = aHiBase + 3 * GARR;

#pragma unroll
        for (int ks = 0; ks < 4; ks++) {
            const uint32_t kb = (uint32_t)(ks * 32);   // k0*2 bytes

            uint32_t ah[2][4], al[2][4];
#pragma unroll
            for (int mf = 0; mf < 2; mf++) {
                ldsm4(ah[mf][0], ah[mf][1], ah[mf][2], ah[mf][3],
                      aHiBase + offA[mf] + kb);
                ldsm4(al[mf][0], al[mf][1], al[mf][2], al[mf][3],
                      aLoBase + offA[mf] + kb);
            }
            uint32_t bhf[4][2], blf[4][2];
#pragma unroll
            for (int np = 0; np < 2; np++) {
                ldsm4(bhf[2 * np][0], bhf[2 * np][1], bhf[2 * np + 1][0], bhf[2 * np + 1][1],
                      bHiBase + offB[np] + kb);
                ldsm4(blf[2 * np][0], blf[2 * np][1], blf[2 * np + 1][0], blf[2 * np + 1][1],
                      bLoBase + offB[np] + kb);
            }
#pragma unroll
            for (int mf = 0; mf < 2; mf++)
#pragma unroll
                for (int nf = 0; nf < 4; nf++) {
                    mma16816(acc[mf][nf], ah[mf][0], ah[mf][1], ah[mf][2], ah[mf][3],
                             bhf[nf][0], bhf[nf][1]);
                    mma16816(acc[mf][nf], ah[mf][0], ah[mf][1], ah[mf][2], ah[mf][3],
                             blf[nf][0], blf[nf][1]);
                    mma16816(acc[mf][nf], al[mf][0], al[mf][1], al[mf][2], al[mf][3],
                             bhf[nf][0], bhf[nf][1]);
                }
        }
        __syncthreads();
    }

#pragma unroll
    for (int mf = 0; mf < 2; mf++) {
        int r0 = m0 + wm + mf * 16 + gr;
        int r1 = r0 + 8;
#pragma unroll
        for (int nf = 0; nf < 4; nf++) {
            int col = n0 + wn + nf * 8 + gc;
            if (col < cfg.N) {
                *reinterpret_cast<float2*>(&cfg.C[(size_t)r0 * cfg.N + col]) =
                    make_float2(acc[mf][nf][0], acc[mf][nf][1]);
                *reinterpret_cast<float2*>(&cfg.C[(size_t)r1 * cfg.N + col]) =
                    make_float2(acc[mf][nf][2], acc[mf][nf][3]);
            }
        }
    }
}

// ---------------------------------------------------------------------------
// fused RoPE + rank contraction for q AND k (z selects), table-driven.
// ---------------------------------------------------------------------------
__global__ void contract_rope2_kernel(
    const float* __restrict__ Aq, const float* __restrict__ Bq,
    __nv_bfloat16* __restrict__ qhi, __nv_bfloat16* __restrict__ qlo,
    const float* __restrict__ Ak, const float* __restrict__ Bk,
    __nv_bfloat16* __restrict__ khi, __nv_bfloat16* __restrict__ klo)
{
    const float* Am; const float* Bm;
    __nv_bfloat16 *hi, *lo;
    int R; float scale;
    if (blockIdx.z == 0) {
        Am = Aq; Bm = Bq; hi = qhi; lo = qlo; R = QRANK; scale = 1.0f / (QRANK * DK);
    } else {
        Am = Ak; Bm = Bk; hi = khi; lo = klo; R = RANK; scale = 1.0f / RANK;
    }

    int idx = blockIdx.x * blockDim.x + threadIdx.x;
    if (idx >= NTOK * HEADS * DK) return;
    int d = idx & (DK - 1);
    int h = (idx >> 6) & (HEADS - 1);
    int t = idx >> 10;

    int i = d & 31;
    int s = t & (SEQ - 1);
    float2 rt = g_rope[(s << 5) + i];
    float cs = rt.x, sn = rt.y;

    const float* a = Am + (size_t)t * (HEADS * R) + h * R;
    const float* b = Bm + (size_t)t * R * DK;
    float sum = 0.f;
    const bool lohalf = (d < 32);
#pragma unroll 6
    for (int r = 0; r < R; r++) {
        float x1 = b[r * DK + i];
        float x2 = b[r * DK + 32 + i];
        float rv = lohalf ? (x1 * cs + x2 * sn) : (-x1 * sn + x2 * cs);
        sum += a[r] * rv;
    }
    sum *= scale;

    int bb = t >> 11;
    size_t o = (((size_t)(bb * HEADS + h)) * SEQ + s) * DK + d;
    __nv_bfloat16 hv = __float2bfloat16(sum);
    hi[o] = hv;
    lo[o] = __float2bfloat16(sum - __bfloat162float(hv));
}

// ---------------------------------------------------------------------------
// fused V contraction + transpose + split -> V^T hi/lo [bh][dk][S]
// ---------------------------------------------------------------------------
__global__ void fvt_kernel(const float* __restrict__ Am,
                           const float* __restrict__ Bm,
                           __nv_bfloat16* __restrict__ hi,
                           __nv_bfloat16* __restrict__ lo)
{
    __shared__ float vt[32][33];
    const int s0 = blockIdx.x * 32, d0 = blockIdx.y * 32;
    const int bh = blockIdx.z;
    const int b = bh >> 4, h = bh & 15;
    const int tx = threadIdx.x, ty = threadIdx.y;

#pragma unroll
    for (int i = 0; i < 4; i++) {
        int ss = ty + i * 8;
        int t = b * SEQ + s0 + ss;
        const float* a = Am + (size_t)t * (HEADS * RANK) + h * RANK;
        const float* bp = Bm + (size_t)t * RANK * DK + d0 + tx;
        vt[tx][ss] = (a[0] * bp[0] + a[1] * bp[DK]) * 0.5f;
    }
    __syncthreads();

#pragma unroll
    for (int i = 0; i < 4; i++) {
        int dd = ty + i * 8;
        float v = vt[dd][tx];
        __nv_bfloat16 hv = __float2bfloat16(v);
        size_t o = ((size_t)bh * DK + d0 + dd) * SEQ + s0 + tx;
        hi[o] = hv;
        lo[o] = __float2bfloat16(v - __bfloat162float(hv));
    }
}

// ---------------------------------------------------------------------------
// HMMA causal flash attention, FQ=128 (8 warps), cp.async 2-stage.
// (unchanged from the 502.3us R14 build)
// ---------------------------------------------------------------------------
#define FPAD   72
#define FARR   (64 * FPAD * 2)
#define FSTAGE (4 * FARR)

__global__ __launch_bounds__(256) void flash_mma_kernel(
    const __nv_bfloat16* __restrict__ Qhi, const __nv_bfloat16* __restrict__ Qlo,
    const __nv_bfloat16* __restrict__ Khi, const __nv_bfloat16* __restrict__ Klo,
    const __nv_bfloat16* __restrict__ Vthi, const __nv_bfloat16* __restrict__ Vtlo,
    __nv_bfloat16* __restrict__ Ohi, __nv_bfloat16* __restrict__ Olo)
{
    extern __shared__ char smem[];
    const uint32_t smem_base = smem_u32(smem);

    const int bh = blockIdx.y;
    const int qb = (gridDim.x - 1) - blockIdx.x;
    const int tid = threadIdx.x;
    const int wid = tid >> 5;
    const int lid = tid & 31;
    const int gr = lid >> 2;
    const int gc = lid & 3;
    const int q0 = qb * 128 + wid * 16;

    int cr[2], cc[2];
    uint32_t sdst[2];
#pragma unroll
    for (int i = 0; i < 2; i++) {
        int idx = tid + i * 256;
        cr[i] = idx >> 3;
        cc[i] = idx & 7;
        sdst[i] = (uint32_t)(cr[i] * (FPAD * 2) + cc[i] * 16);
    }

    uint32_t qfh[4][4], qfl[4][4];
#pragma unroll
    for (int ks = 0; ks < 4; ks++)
#pragma unroll
        for (int i = 0; i < 4; i++) {
            int row = q0 + gr + (i & 1) * 8;
            int col = ks * 16 + gc * 2 + (i >> 1) * 8;
            size_t g = ((size_t)bh * SEQ + row) * DK + col;
            qfh[ks][i] = *reinterpret_cast<const uint32_t*>(&Qhi[g]);
            qfl[ks][i] = *reinterpret_cast<const uint32_t*>(&Qlo[g]);
        }

    float accO[8][4];
#pragma unroll
    for (int nf = 0; nf < 8; nf++)
#pragma unroll
        for (int e = 0; e < 4; e++) accO[nf][e] = 0.f;
    float m0 = -INFINITY, m1 = -INFINITY, l0 = 0.f, l1 = 0.f;

    const char* pKhi = reinterpret_cast<const char*>(Khi);
    const char* pKlo = reinterpret_cast<const char*>(Klo);
    const char* pVhi = reinterpret_cast<const char*>(Vthi);
    const char* pVlo = reinterpret_cast<const char*>(Vtlo);

    auto issue = [&](int kt, int st) {
        uint32_t s0a = smem_base + st * FSTAGE;
#pragma unroll
        for (int i = 0; i < 2; i++) {
            size_t gk = 2 * (((size_t)bh * SEQ + kt * 64 + cr[i]) * DK + cc[i] * 8);
            CP_ASYNC16(s0a + sdst[i],            pKhi + gk);
            CP_ASYNC16(s0a + FARR + sdst[i],     pKlo + gk);
            size_t gv = 2 * (((size_t)bh * DK + cr[i]) * SEQ + kt * 64 + cc[i] * 8);
            CP_ASYNC16(s0a + 2 * FARR + sdst[i], pVhi + gv);
            CP_ASYNC16(s0a + 3 * FARR + sdst[i], pVlo + gv);
        }
        CP_COMMIT();
    };

    const int ktmax = 2 * qb + 1;
    issue(0, 0);

    for (int kt = 0; kt <= ktmax; kt++) {
        const int st = kt & 1;
        if (kt < ktmax) { issue(kt + 1, st ^ 1); CP_WAIT1(); }
        else            { CP_WAIT0(); }
        __syncthreads();

        const int kg0 = kt * 64;
        if (kg0 <= q0 + 15) {
            const uint32_t* uKhi = reinterpret_cast<const uint32_t*>(smem + st * FSTAGE);
            const uint32_t* uKlo = reinterpret_cast<const uint32_t*>(smem + st * FSTAGE + FARR);
            const uint32_t* uVhi = reinterpret_cast<const uint32_t*>(smem + st * FSTAGE + 2 * FARR);
            const uint32_t* uVlo = reinterpret_cast<const uint32_t*>(smem + st * FSTAGE + 3 * FARR);

            float sacc[8][4];
#pragma unroll
            for (int nf = 0; nf < 8; nf++)
#pragma unroll
                for (int e = 0; e < 4; e++) sacc[nf][e] = 0.f;

#pragma unroll
            for (int ks = 0; ks < 4; ks++) {
#pragma unroll
                for (int nf = 0; nf < 8; nf++) {
                    int w = (nf * 8 + gr) * 36 + ks * 8 + gc;
                    uint32_t b0 = uKhi[w], b1 = uKhi[w + 4];
                    uint32_t c0 = uKlo[w], c1 = uKlo[w + 4];
                    mma16816(sacc[nf], qfh[ks][0], qfh[ks][1], qfh[ks][2], qfh[ks][3], b0, b1);
                    mma16816(sacc[nf], qfh[ks][0], qfh[ks][1], qfh[ks][2], qfh[ks][3], c0, c1);
                    mma16816(sacc[nf], qfl[ks][0], qfl[ks][1], qfl[ks][2], qfl[ks][3], b0, b1);
                }
            }

            if (kg0 + 63 > q0) {
#pragma unroll
                for (int nf = 0; nf < 8; nf++) {
                    int key = kg0 + nf * 8 + gc * 2;
                    int r0 = q0 + gr, r1 = r0 + 8;
                    if (key > r0)     sacc[nf][0] = -INFINITY;
                    if (key + 1 > r0) sacc[nf][1] = -INFINITY;
                    if (key > r1)     sacc[nf][2] = -INFINITY;
                    if (key + 1 > r1) sacc[nf][3] = -INFINITY;
                }
            }

            float mx0 = -INFINITY, mx1 = -INFINITY;
#pragma unroll
            for (int nf = 0; nf < 8; nf++) {
                mx0 = fmaxf(mx0, fmaxf(sacc[nf][0], sacc[nf][1]));
                mx1 = fmaxf(mx1, fmaxf(sacc[nf][2], sacc[nf][3]));
            }
            mx0 = fmaxf(mx0, __shfl_xor_sync(0xffffffffu, mx0, 1));
            mx0 = fmaxf(mx0, __shfl_xor_sync(0xffffffffu, mx0, 2));
            mx1 = fmaxf(mx1, __shfl_xor_sync(0xffffffffu, mx1, 1));
            mx1 = fmaxf(mx1, __shfl_xor_sync(0xffffffffu, mx1, 2));

            float mn0 = fmaxf(m0, mx0), mn1 = fmaxf(m1, mx1);
            float f0 = __expf(m0 - mn0), f1 = __expf(m1 - mn1);
            m0 = mn0; m1 = mn1;

            float sum0 = 0.f, sum1 = 0.f;
#pragma unroll
            for (int nf = 0; nf < 8; nf++) {
                sacc[nf][0] = __expf(sacc[nf][0] - mn0);
                sacc[nf][1] = __expf(sacc[nf][1] - mn0);
                sacc[nf][2] = __expf(sacc[nf][2] - mn1);
                sacc[nf][3] = __expf(sacc[nf][3] - mn1);
                sum0 += sacc[nf][0] + sacc[nf][1];
                sum1 += sacc[nf][2] + sacc[nf][3];
            }
            sum0 += __shfl_xor_sync(0xffffffffu, sum0, 1);
            sum0 += __shfl_xor_sync(0xffffffffu, sum0, 2);
            sum1 += __shfl_xor_sync(0xffffffffu, sum1, 1);
            sum1 += __shfl_xor_sync(0xffffffffu, sum1, 2);
            l0 = l0 * f0 + sum0;
            l1 = l1 * f1 + sum1;

#pragma unroll
            for (int nf = 0; nf < 8; nf++) {
                accO[nf][0] *= f0; accO[nf][1] *= f0;
                accO[nf][2] *= f1; accO[nf][3] *= f1;
            }

            uint32_t pah[4][4], pal[4][4];
#pragma unroll
            for (int j = 0; j < 4; j++) {
                float p00 = sacc[2 * j][0],     p01 = sacc[2 * j][1];
                float p02 = sacc[2 * j][2],     p03 = sacc[2 * j][3];
                float p10 = sacc[2 * j + 1][0], p11 = sacc[2 * j + 1][1];
                float p12 = sacc[2 * j + 1][2], p13 = sacc[2 * j + 1][3];
                pah[j][0] = packbf2(p00, p01);
                pah[j][1] = packbf2(p02, p03);
                pah[j][2] = packbf2(p10, p11);
                pah[j][3] = packbf2(p12, p13);
                pal[j][0] = packbf2(p00 - __bfloat162float(__float2bfloat16(p00)),
                                    p01 - __bfloat162float(__float2bfloat16(p01)));
                pal[j][1] = packbf2(p02 - __bfloat162float(__float2bfloat16(p02)),
                                    p03 - __bfloat162float(__float2bfloat16(p03)));
                pal[j][2] = packbf2(p10 - __bfloat162float(__float2bfloat16(p10)),
                                    p11 - __bfloat162float(__float2bfloat16(p11)));
                pal[j][3] = packbf2(p12 - __bfloat162float(__float2bfloat16(p12)),
                                    p13 - __bfloat162float(__float2bfloat16(p13)));
            }

#pragma unroll
            for (int ks = 0; ks < 4; ks++) {
#pragma unroll
                for (int nf = 0; nf < 8; nf++) {
                    int w = (nf * 8 + gr) * 36 + ks * 8 + gc;
                    uint32_t v0 = uVhi[w], v1 = uVhi[w + 4];
                    uint32_t u0 = uVlo[w], u1 = uVlo[w + 4];
                    mma16816(accO[nf], pah[ks][0], pah[ks][1], pah[ks][2], pah[ks][3], v0, v1);
                    mma16816(accO[nf], pah[ks][0], pah[ks][1], pah[ks][2], pah[ks][3], u0, u1);
                    mma16816(accO[nf], pal[ks][0], pal[ks][1], pal[ks][2], pal[ks][3], v0, v1);
                }
            }
        }
        __syncthreads();
    }

    const int b = bh >> 4;
    const int h = bh & 15;
    const float inv0 = 1.0f / l0, inv1 = 1.0f / l1;
    const int r0 = q0 + gr, r1 = r0 + 8;
#pragma unroll
    for (int nf = 0; nf < 8; nf++) {
        int col = h * DK + nf * 8 + gc * 2;
        size_t o0 = ((size_t)(b * SEQ) + r0) * DMODEL + col;
        size_t o1 = ((size_t)(b * SEQ) + r1) * DMODEL + col;
        float v00 = accO[nf][0] * inv0, v01 = accO[nf][1] * inv0;
        float v10 = accO[nf][2] * inv1, v11 = accO[nf][3] * inv1;
        *reinterpret_cast<uint32_t*>(&Ohi[o0]) = packbf2(v00, v01);
        *reinterpret_cast<uint32_t*>(&Ohi[o1]) = packbf2(v10, v11);
        *reinterpret_cast<uint32_t*>(&Olo[o0]) =
            packbf2(v00 - __bfloat162float(__float2bfloat16(v00)),
                    v01 - __bfloat162float(__float2bfloat16(v01)));
        *reinterpret_cast<uint32_t*>(&Olo[o1]) =
            packbf2(v10 - __bfloat162float(__float2bfloat16(v10)),
                    v11 - __bfloat162float(__float2bfloat16(v11)));
    }
}

// ---------------------------------------------------------------------------
extern "C" void kernel_launch(void* const* d_in, const int* in_sizes, int n_in,
                              void* d_out, int out_size)
{
    const float* q    = (const float*)d_in[0];
    const float* k    = (const float*)d_in[1];
    const float* v    = (const float*)d_in[2];
    const float* W_Aq = (const float*)d_in[4];
    const float* W_Ak = (const float*)d_in[5];
    const float* W_Av = (const float*)d_in[6];
    const float* W_Bq = (const float*)d_in[7];
    const float* W_Bk = (const float*)d_in[8];
    const float* W_Bv = (const float*)d_in[9];
    const float* Wo   = (const float*)d_in[10];
    float* out = (float*)d_out;

    float* scratch = nullptr;
    cudaGetSymbolAddress((void**)&scratch, g_scratch);
    __nv_bfloat16* bs = nullptr;
    cudaGetSymbolAddress((void**)&bs, g_bf);

    float* sAq = scratch + OFF_AQ;
    float* sAk = scratch + OFF_AK;
    float* sAv = scratch + OFF_AV;
    float* sBq = scratch + OFF_BQ;
    float* sBk = scratch + OFF_BK;
    float* sBv = scratch + OFF_BV;

    const int GEMSMEM = 2 * GSTAGE;         // 147456
    const int FLSMEM  = 2 * FSTAGE;         // 73728
    cudaFuncSetAttribute(tc_gemm_kernel,
                         cudaFuncAttributeMaxDynamicSharedMemorySize, GEMSMEM);
    cudaFuncSetAttribute(flash_mma_kernel,
                         cudaFuncAttributeMaxDynamicSharedMemorySize, FLSMEM);

    const int MY = NTOK / 128;   // 32

    // 0) rope table + input splits + weight transpose-splits
    rope_table_kernel<<<(SEQ * 32 + 255) / 256, 256>>>();
    split3_kernel<<<dim3((TOKD + 255) / 256, 1, 3), 256>>>(
        q, k, v, bs + BOFF_QHI, bs + BOFF_QLO, bs + BOFF_KHI, bs + BOFF_KLO,
        bs + BOFF_VHI, bs + BOFF_VLO, TOKD);

    TsCfg7 ts;
    ts.c[0] = { W_Bq, bs + BOFF_WBQ_HI, bs + BOFF_WBQ_LO, 384, 384 };
    ts.c[1] = { W_Bk, bs + BOFF_WBK_HI, bs + BOFF_WBK_LO, 128, 128 };
    ts.c[2] = { W_Bv, bs + BOFF_WBV_HI, bs + BOFF_WBV_LO, 128, 128 };
    ts.c[3] = { Wo,   bs + BOFF_WO_HI,  bs + BOFF_WO_LO,  1024, 1024 };
    ts.c[4] = { W_Aq, bs + BOFF_WAQ_HI, bs + BOFF_WAQ_LO, 96, 128 };
    ts.c[5] = { W_Ak, bs + BOFF_WAK_HI, bs + BOFF_WAK_LO, 32, 128 };
    ts.c[6] = { W_Av, bs + BOFF_WAV_HI, bs + BOFF_WAV_LO, 32, 128 };
    tsplit7_kernel<<<dim3(32, 32, 7), dim3(32, 8)>>>(ts);

    // 1) all 6 projections in one pipelined HMMA launch (512 threads)
    GemmCfg6 gp;
    gp.c[0] = { bs + BOFF_QHI, bs + BOFF_QLO, bs + BOFF_WBQ_HI, bs + BOFF_WBQ_LO, sBq, 384, 384 };
    gp.c[1] = { bs + BOFF_KHI, bs + BOFF_KLO, bs + BOFF_WBK_HI, bs + BOFF_WBK_LO, sBk, 128, 128 };
    gp.c[2] = { bs + BOFF_VHI, bs + BOFF_VLO, bs + BOFF_WBV_HI, bs + BOFF_WBV_LO, sBv, 128, 128 };
    gp.c[3] = { bs + BOFF_QHI, bs + BOFF_QLO, bs + BOFF_WAQ_HI, bs + BOFF_WAQ_LO, sAq, 96, 128 };
    gp.c[4] = { bs + BOFF_KHI, bs + BOFF_KLO, bs + BOFF_WAK_HI, bs + BOFF_WAK_LO, sAk, 32, 128 };
    gp.c[5] = { bs + BOFF_VHI, bs + BOFF_VLO, bs + BOFF_WAV_HI, bs + BOFF_WAV_LO, sAv, 32, 128 };
    tc_gemm_kernel<<<dim3(3, MY, 6), 512, GEMSMEM>>>(gp);

    // 2) fused RoPE + contraction (q & k) and V contraction+transpose
    {
        int total = NTOK * HEADS * DK;
        contract_rope2_kernel<<<dim3((total + 255) / 256, 1, 2), 256>>>(
            sAq, sBq, bs + BOFF_FQHI, bs + BOFF_FQLO,
            sAk, sBk, bs + BOFF_FKHI, bs + BOFF_FKLO);
        fvt_kernel<<<dim3(SEQ / 32, DK / 32, BH), dim3(32, 8)>>>(
            sAv, sBv, bs + BOFF_FVTHI, bs + BOFF_FVTLO);
    }

    // 3) HMMA causal flash attention (FQ=128)
    flash_mma_kernel<<<dim3(SEQ / 128, BH), 256, FLSMEM>>>(
        bs + BOFF_FQHI, bs + BOFF_FQLO, bs + BOFF_FKHI, bs + BOFF_FKLO,
        bs + BOFF_FVTHI, bs + BOFF_FVTLO, bs + BOFF_OAHI, bs + BOFF_OALO);

    // 4) output projection (512 threads)
    GemmCfg6 go;
    go.c[0] = { bs + BOFF_OAHI, bs + BOFF_OALO, bs + BOFF_WO_HI, bs + BOFF_WO_LO, out, 1024, 1024 };
    go.c[1] = go.c[0]; go.c[2] = go.c[0]; go.c[3] = go.c[0]; go.c[4] = go.c[0]; go.c[5] = go.c[0];
    tc_gemm_kernel<<<dim3(8, MY, 1), 512, GEMSMEM>>>(go);
}

// round 16
// speedup vs baseline: 1.0181x; 1.0181x over previous
#include <cuda_runtime.h>
#include <cuda_bf16.h>
#include <math.h>
#include <stdint.h>

// ---------------------------------------------------------------------------
// T6Attention — round 16: R15 + flash __launch_bounds__(256,2) (2 CTAs/SM)
// B=2, S=2048, D_MODEL=1024, HEADS=16, DK=64, Q_RANK=6, RANK=2
// ---------------------------------------------------------------------------

#define BATCH     2
#define SEQ       2048
#define DMODEL    1024
#define HEADS     16
#define DK        64
#define QRANK     6
#define RANK      2
#define NTOK      (BATCH*SEQ)        // 4096
#define BH        (BATCH*HEADS)      // 32

// fp32 scratch offsets
#define OFF_AQ   0
#define SZ_AQ    (NTOK*HEADS*QRANK)
#define OFF_AK   (OFF_AQ+SZ_AQ)
#define SZ_AK    (NTOK*HEADS*RANK)
#define OFF_AV   (OFF_AK+SZ_AK)
#define SZ_AV    SZ_AK
#define OFF_BQ   (OFF_AV+SZ_AV)
#define SZ_BQ    (NTOK*QRANK*DK)
#define OFF_BK   (OFF_BQ+SZ_BQ)
#define SZ_BK    (NTOK*RANK*DK)
#define OFF_BV   (OFF_BK+SZ_BK)
#define SZ_BV    SZ_BK
#define SCRATCH_TOTAL (OFF_BV+SZ_BV)

__device__ float g_scratch[SCRATCH_TOTAL];
__device__ float2 g_rope[SEQ * 32];

// bf16 scratch offsets (elements)
#define TOKD          (NTOK*DMODEL)
#define BOFF_QHI      0
#define BOFF_QLO      (BOFF_QHI + TOKD)
#define BOFF_KHI      (BOFF_QLO + TOKD)
#define BOFF_KLO      (BOFF_KHI + TOKD)
#define BOFF_VHI      (BOFF_KLO + TOKD)
#define BOFF_VLO      (BOFF_VHI + TOKD)
#define BOFF_OAHI     (BOFF_VLO + TOKD)
#define BOFF_OALO     (BOFF_OAHI + TOKD)
#define BOFF_WBQ_HI   (BOFF_OALO + TOKD)
#define BOFF_WBQ_LO   (BOFF_WBQ_HI + 384*1024)
#define BOFF_WBK_HI   (BOFF_WBQ_LO + 384*1024)
#define BOFF_WBK_LO   (BOFF_WBK_HI + 128*1024)
#define BOFF_WBV_HI   (BOFF_WBK_LO + 128*1024)
#define BOFF_WBV_LO   (BOFF_WBV_HI + 128*1024)
#define BOFF_WO_HI    (BOFF_WBV_LO + 128*1024)
#define BOFF_WO_LO    (BOFF_WO_HI + 1024*1024)
#define BOFF_WAQ_HI   (BOFF_WO_LO + 1024*1024)
#define BOFF_WAQ_LO   (BOFF_WAQ_HI + 128*1024)
#define BOFF_WAK_HI   (BOFF_WAQ_LO + 128*1024)
#define BOFF_WAK_LO   (BOFF_WAK_HI + 128*1024)
#define BOFF_WAV_HI   (BOFF_WAK_LO + 128*1024)
#define BOFF_WAV_LO   (BOFF_WAV_HI + 128*1024)
#define BOFF_FQHI     (BOFF_WAV_LO + 128*1024)
#define BOFF_FQLO     (BOFF_FQHI + TOKD)
#define BOFF_FKHI     (BOFF_FQLO + TOKD)
#define BOFF_FKLO     (BOFF_FKHI + TOKD)
#define BOFF_FVTHI    (BOFF_FKLO + TOKD)
#define BOFF_FVTLO    (BOFF_FVTHI + TOKD)
#define BF_TOTAL      (BOFF_FVTLO + TOKD)

__device__ __nv_bfloat16 g_bf[BF_TOTAL];

// ---------------------------------------------------------------------------
// helpers
// ---------------------------------------------------------------------------
__device__ __forceinline__ void mma16816(float* d,
                                         uint32_t a0, uint32_t a1, uint32_t a2, uint32_t a3,
                                         uint32_t b0, uint32_t b1)
{
    asm volatile(
        "mma.sync.aligned.m16n8k16.row.col.f32.bf16.bf16.f32 "
        "{%0,%1,%2,%3}, {%4,%5,%6,%7}, {%8,%9}, {%0,%1,%2,%3};"
        : "+f"(d[0]), "+f"(d[1]), "+f"(d[2]), "+f"(d[3])
        : "r"(a0), "r"(a1), "r"(a2), "r"(a3), "r"(b0), "r"(b1));
}

__device__ __forceinline__ void ldsm4(uint32_t& r0, uint32_t& r1,
                                      uint32_t& r2, uint32_t& r3, uint32_t addr)
{
    asm volatile("ldmatrix.sync.aligned.m8n8.x4.shared.b16 {%0,%1,%2,%3}, [%4];"
        : "=r"(r0), "=r"(r1), "=r"(r2), "=r"(r3) : "r"(addr));
}

__device__ __forceinline__ uint32_t packbf2(float a, float b) {
    __nv_bfloat162 t = __floats2bfloat162_rn(a, b);
    return *reinterpret_cast<uint32_t*>(&t);
}

__device__ __forceinline__ uint32_t smem_u32(const void* p) {
    return (uint32_t)__cvta_generic_to_shared(p);
}

#define CP_ASYNC16(dst_u32, src_ptr) \
    asm volatile("cp.async.cg.shared.global [%0], [%1], 16;" \
        :: "r"(dst_u32), "l"(src_ptr) : "memory")
#define CP_COMMIT() asm volatile("cp.async.commit_group;" ::: "memory")
#define CP_WAIT0()  asm volatile("cp.async.wait_group 0;" ::: "memory")
#define CP_WAIT1()  asm volatile("cp.async.wait_group 1;" ::: "memory")

// ---------------------------------------------------------------------------
// RoPE table
// ---------------------------------------------------------------------------
__global__ void rope_table_kernel()
{
    int idx = blockIdx.x * blockDim.x + threadIdx.x;
    if (idx >= SEQ * 32) return;
    int s = idx >> 5;
    int i = idx & 31;
    float inv_freq = powf(10000.0f, -(float)(2 * i) / 64.0f);
    float fr = (float)s * inv_freq;
    float sn, cs;
    sincosf(fr, &sn, &cs);
    g_rope[idx] = make_float2(cs, sn);
}

// ---------------------------------------------------------------------------
// batched hi/lo split for q,k,v
// ---------------------------------------------------------------------------
__global__ void split3_kernel(const float* __restrict__ x0, const float* __restrict__ x1,
                              const float* __restrict__ x2,
                              __nv_bfloat16* __restrict__ h0, __nv_bfloat16* __restrict__ l0p,
                              __nv_bfloat16* __restrict__ h1, __nv_bfloat16* __restrict__ l1p,
                              __nv_bfloat16* __restrict__ h2, __nv_bfloat16* __restrict__ l2p,
                              int n)
{
    const float* x = x0; __nv_bfloat16* hi = h0; __nv_bfloat16* lo = l0p;
    if (blockIdx.z == 1) { x = x1; hi = h1; lo = l1p; }
    else if (blockIdx.z == 2) { x = x2; hi = h2; lo = l2p; }
    int i = blockIdx.x * blockDim.x + threadIdx.x;
    if (i >= n) return;
    float v = x[i];
    __nv_bfloat16 h = __float2bfloat16(v);
    hi[i] = h;
    lo[i] = __float2bfloat16(v - __bfloat162float(h));
}

// ---------------------------------------------------------------------------
// batched transpose + split with zero padding: W[1024,N] -> hi/lo [Npad,1024]
// ---------------------------------------------------------------------------
struct TsCfg {
    const float* W;
    __nv_bfloat16* hi;
    __nv_bfloat16* lo;
    int N;
    int Npad;
};
struct TsCfg7 { TsCfg c[7]; };

__global__ void tsplit7_kernel(TsCfg7 p)
{
    TsCfg cfg = p.c[blockIdx.z];
    const int n0 = blockIdx.x * 32, k0 = blockIdx.y * 32;
    if (n0 >= cfg.Npad) return;
    const int tx = threadIdx.x, ty = threadIdx.y;

    if (n0 >= cfg.N) {
#pragma unroll
        for (int i = 0; i < 4; i++) {
            size_t o = (size_t)(n0 + ty + i * 8) * 1024 + k0 + tx;
            cfg.hi[o] = __float2bfloat16(0.f);
            cfg.lo[o] = __float2bfloat16(0.f);
        }
        return;
    }

    __shared__ float t[32][33];
#pragma unroll
    for (int i = 0; i < 4; i++)
        t[ty + i * 8][tx] = cfg.W[(size_t)(k0 + ty + i * 8) * cfg.N + n0 + tx];
    __syncthreads();
#pragma unroll
    for (int i = 0; i < 4; i++) {
        float v = t[tx][ty + i * 8];
        __nv_bfloat16 h = __float2bfloat16(v);
        size_t o = (size_t)(n0 + ty + i * 8) * 1024 + k0 + tx;
        cfg.hi[o] = h;
        cfg.lo[o] = __float2bfloat16(v - __bfloat162float(h));
    }
}

// ---------------------------------------------------------------------------
// HMMA GEMM (R15 config): 512 threads, 16 warps (4M x 4N), warp tile 32x32,
// cp.async 2-stage, ldmatrix loads. At the measured mma.sync ceiling.
// ---------------------------------------------------------------------------
#define KPAD   72
#define GARR   (128 * KPAD * 2)
#define GSTAGE (4 * GARR)

struct GemmCfg {
    const __nv_bfloat16 *Ahi, *Alo, *Bhi, *Blo;
    float* C;
    int N;
    int Npad;
};
struct GemmCfg6 { GemmCfg c[6]; };

__global__ __launch_bounds__(512) void tc_gemm_kernel(GemmCfg6 p)
{
    GemmCfg cfg = p.c[blockIdx.z];
    const int n0 = blockIdx.x * 128;
    if (n0 >= cfg.Npad) return;

    extern __shared__ char smem[];
    const uint32_t smem_base = smem_u32(smem);

    const int tid = threadIdx.x;
    const int wid = tid >> 5;
    const int lid = tid & 31;
    const int m0 = blockIdx.y * 128;
    const int wm = (wid & 3) * 32;
    const int wn = (wid >> 2) * 32;
    const int gr = lid >> 2;
    const int gc = (lid & 3) * 2;

    const int laneRowA  = (lid & 7) + ((lid >> 3) & 1) * 8;
    const int laneKoffA = (lid >> 4) * 8;
    const int laneRowB  = (lid & 7) + (lid >> 4) * 8;
    const int laneKoffB = ((lid >> 3) & 1) * 8;

    uint32_t offA[2], offB[2];
#pragma unroll
    for (int mf = 0; mf < 2; mf++)
        offA[mf] = (uint32_t)(((wm + mf * 16 + laneRowA) * KPAD + laneKoffA) * 2);
#pragma unroll
    for (int np = 0; np < 2; np++)
        offB[np] = (uint32_t)(((wn + np * 16 + laneRowB) * KPAD + laneKoffB) * 2);

    const char* pAhi = reinterpret_cast<const char*>(cfg.Ahi);
    const char* pAlo = reinterpret_cast<const char*>(cfg.Alo);
    const char* pBhi = reinterpret_cast<const char*>(cfg.Bhi);
    const char* pBlo = reinterpret_cast<const char*>(cfg.Blo);

    int cr[2], cc[2];
    uint32_t sdst[2];
#pragma unroll
    for (int i = 0; i < 2; i++) {
        int idx = tid + i * 512;
        cr[i] = idx >> 3;
        cc[i] = idx & 7;
        sdst[i] = (uint32_t)(cr[i] * (KPAD * 2) + cc[i] * 16);
    }

    auto issue = [&](int kc, int st) {
        uint32_t s0a = smem_base + st * GSTAGE;
#pragma unroll
        for (int i = 0; i < 2; i++) {
            size_t ga = 2 * ((size_t)(m0 + cr[i]) * 1024 + kc * 64 + cc[i] * 8);
            CP_ASYNC16(s0a + sdst[i],            pAhi + ga);
            CP_ASYNC16(s0a + GARR + sdst[i],     pAlo + ga);
            size_t gb = 2 * ((size_t)(n0 + cr[i]) * 1024 + kc * 64 + cc[i] * 8);
            CP_ASYNC16(s0a + 2 * GARR + sdst[i], pBhi + gb);
            CP_ASYNC16(s0a + 3 * GARR + sdst[i], pBlo + gb);
        }
        CP_COMMIT();
    };

    float acc[2][4][4];
#pragma unroll
    for (int mf = 0; mf < 2; mf++)
#pragma unroll
        for (int nf = 0; nf < 4; nf++)
#pragma unroll
            for (int e = 0; e < 4; e++) acc[mf][nf][e] = 0.f;

    issue(0, 0);

    for (int kc = 0; kc < 16; kc++) {
        const int st = kc & 1;
        if (kc + 1 < 16) { issue(kc + 1, st ^ 1); CP_WAIT1(); }
        else             { CP_WAIT0(); }
        __syncthreads();

        const uint32_t aHiBase = smem_base + st * GSTAGE;
        const uint32_t aLoBase = aHiBase + GARR;
        const uint32_t bHiBase = aHiBase + 2 * GARR;
        const uint32_t bLoBase = aHiBase + 3 * GARR;

#pragma unroll
        for (int ks = 0; ks < 4; ks++) {
            const uint32_t kb = (uint32_t)(ks * 32);

            uint32_t ah[2][4], al[2][4];
#pragma unroll
            for (int mf = 0; mf < 2; mf++) {
                ldsm4(ah[mf][0], ah[mf][1], ah[mf][2], ah[mf][3],
                      aHiBase + offA[mf] + kb);
                ldsm4(al[mf][0], al[mf][1], al[mf][2], al[mf][3],
                      aLoBase + offA[mf] + kb);
            }
            uint32_t bhf[4][2], blf[4][2];
#pragma unroll
            for (int np = 0; np < 2; np++) {
                ldsm4(bhf[2 * np][0], bhf[2 * np][1], bhf[2 * np + 1][0], bhf[2 * np + 1][1],
                      bHiBase + offB[np] + kb);
                ldsm4(blf[2 * np][0], blf[2 * np][1], blf[2 * np + 1][0], blf[2 * np + 1][1],
                      bLoBase + offB[np] + kb);
            }
#pragma unroll
            for (int mf = 0; mf < 2; mf++)
#pragma unroll
                for (int nf = 0; nf < 4; nf++) {
                    mma16816(acc[mf][nf], ah[mf][0], ah[mf][1], ah[mf][2], ah[mf][3],
                             bhf[nf][0], bhf[nf][1]);
                    mma16816(acc[mf][nf], ah[mf][0], ah[mf][1], ah[mf][2], ah[mf][3],
                             blf[nf][0], blf[nf][1]);
                    mma16816(acc[mf][nf], al[mf][0], al[mf][1], al[mf][2], al[mf][3],
                             bhf[nf][0], bhf[nf][1]);
                }
        }
        __syncthreads();
    }

#pragma unroll
    for (int mf = 0; mf < 2; mf++) {
        int r0 = m0 + wm + mf * 16 + gr;
        int r1 = r0 + 8;
#pragma unroll
        for (int nf = 0; nf < 4; nf++) {
            int col = n0 + wn + nf * 8 + gc;
            if (col < cfg.N) {
                *reinterpret_cast<float2*>(&cfg.C[(size_t)r0 * cfg.N + col]) =
                    make_float2(acc[mf][nf][0], acc[mf][nf][1]);
                *reinterpret_cast<float2*>(&cfg.C[(size_t)r1 * cfg.N + col]) =
                    make_float2(acc[mf][nf][2], acc[mf][nf][3]);
            }
        }
    }
}

// ---------------------------------------------------------------------------
// fused RoPE + rank contraction for q AND k (z selects), table-driven.
// ---------------------------------------------------------------------------
__global__ void contract_rope2_kernel(
    const float* __restrict__ Aq, const float* __restrict__ Bq,
    __nv_bfloat16* __restrict__ qhi, __nv_bfloat16* __restrict__ qlo,
    const float* __restrict__ Ak, const float* __restrict__ Bk,
    __nv_bfloat16* __restrict__ khi, __nv_bfloat16* __restrict__ klo)
{
    const float* Am; const float* Bm;
    __nv_bfloat16 *hi, *lo;
    int R; float scale;
    if (blockIdx.z == 0) {
        Am = Aq; Bm = Bq; hi = qhi; lo = qlo; R = QRANK; scale = 1.0f / (QRANK * DK);
    } else {
        Am = Ak; Bm = Bk; hi = khi; lo = klo; R = RANK; scale = 1.0f / RANK;
    }

    int idx = blockIdx.x * blockDim.x + threadIdx.x;
    if (idx >= NTOK * HEADS * DK) return;
    int d = idx & (DK - 1);
    int h = (idx >> 6) & (HEADS - 1);
    int t = idx >> 10;

    int i = d & 31;
    int s = t & (SEQ - 1);
    float2 rt = g_rope[(s << 5) + i];
    float cs = rt.x, sn = rt.y;

    const float* a = Am + (size_t)t * (HEADS * R) + h * R;
    const float* b = Bm + (size_t)t * R * DK;
    float sum = 0.f;
    const bool lohalf = (d < 32);
#pragma unroll 6
    for (int r = 0; r < R; r++) {
        float x1 = b[r * DK + i];
        float x2 = b[r * DK + 32 + i];
        float rv = lohalf ? (x1 * cs + x2 * sn) : (-x1 * sn + x2 * cs);
        sum += a[r] * rv;
    }
    sum *= scale;

    int bb = t >> 11;
    size_t o = (((size_t)(bb * HEADS + h)) * SEQ + s) * DK + d;
    __nv_bfloat16 hv = __float2bfloat16(sum);
    hi[o] = hv;
    lo[o] = __float2bfloat16(sum - __bfloat162float(hv));
}

// ---------------------------------------------------------------------------
// fused V contraction + transpose + split -> V^T hi/lo [bh][dk][S]
// ---------------------------------------------------------------------------
__global__ void fvt_kernel(const float* __restrict__ Am,
                           const float* __restrict__ Bm,
                           __nv_bfloat16* __restrict__ hi,
                           __nv_bfloat16* __restrict__ lo)
{
    __shared__ float vt[32][33];
    const int s0 = blockIdx.x * 32, d0 = blockIdx.y * 32;
    const int bh = blockIdx.z;
    const int b = bh >> 4, h = bh & 15;
    const int tx = threadIdx.x, ty = threadIdx.y;

#pragma unroll
    for (int i = 0; i < 4; i++) {
        int ss = ty + i * 8;
        int t = b * SEQ + s0 + ss;
        const float* a = Am + (size_t)t * (HEADS * RANK) + h * RANK;
        const float* bp = Bm + (size_t)t * RANK * DK + d0 + tx;
        vt[tx][ss] = (a[0] * bp[0] + a[1] * bp[DK]) * 0.5f;
    }
    __syncthreads();

#pragma unroll
    for (int i = 0; i < 4; i++) {
        int dd = ty + i * 8;
        float v = vt[dd][tx];
        __nv_bfloat16 hv = __float2bfloat16(v);
        size_t o = ((size_t)bh * DK + d0 + dd) * SEQ + s0 + tx;
        hi[o] = hv;
        lo[o] = __float2bfloat16(v - __bfloat162float(hv));
    }
}

// ---------------------------------------------------------------------------
// HMMA causal flash attention, FQ=128 (8 warps), cp.async 2-stage.
// NEW: __launch_bounds__(256, 2) — force 2 CTAs/SM (regs capped at 128).
// ---------------------------------------------------------------------------
#define FPAD   72
#define FARR   (64 * FPAD * 2)
#define FSTAGE (4 * FARR)

__global__ __launch_bounds__(256, 2) void flash_mma_kernel(
    const __nv_bfloat16* __restrict__ Qhi, const __nv_bfloat16* __restrict__ Qlo,
    const __nv_bfloat16* __restrict__ Khi, const __nv_bfloat16* __restrict__ Klo,
    const __nv_bfloat16* __restrict__ Vthi, const __nv_bfloat16* __restrict__ Vtlo,
    __nv_bfloat16* __restrict__ Ohi, __nv_bfloat16* __restrict__ Olo)
{
    extern __shared__ char smem[];
    const uint32_t smem_base = smem_u32(smem);

    const int bh = blockIdx.y;
    const int qb = (gridDim.x - 1) - blockIdx.x;
    const int tid = threadIdx.x;
    const int wid = tid >> 5;
    const int lid = tid & 31;
    const int gr = lid >> 2;
    const int gc = lid & 3;
    const int q0 = qb * 128 + wid * 16;

    int cr[2], cc[2];
    uint32_t sdst[2];
#pragma unroll
    for (int i = 0; i < 2; i++) {
        int idx = tid + i * 256;
        cr[i] = idx >> 3;
        cc[i] = idx & 7;
        sdst[i] = (uint32_t)(cr[i] * (FPAD * 2) + cc[i] * 16);
    }

    uint32_t qfh[4][4], qfl[4][4];
#pragma unroll
    for (int ks = 0; ks < 4; ks++)
#pragma unroll
        for (int i = 0; i < 4; i++) {
            int row = q0 + gr + (i & 1) * 8;
            int col = ks * 16 + gc * 2 + (i >> 1) * 8;
            size_t g = ((size_t)bh * SEQ + row) * DK + col;
            qfh[ks][i] = *reinterpret_cast<const uint32_t*>(&Qhi[g]);
            qfl[ks][i] = *reinterpret_cast<const uint32_t*>(&Qlo[g]);
        }

    float accO[8][4];
#pragma unroll
    for (int nf = 0; nf < 8; nf++)
#pragma unroll
        for (int e = 0; e < 4; e++) accO[nf][e] = 0.f;
    float m0 = -INFINITY, m1 = -INFINITY, l0 = 0.f, l1 = 0.f;

    const char* pKhi = reinterpret_cast<const char*>(Khi);
    const char* pKlo = reinterpret_cast<const char*>(Klo);
    const char* pVhi = reinterpret_cast<const char*>(Vthi);
    const char* pVlo = reinterpret_cast<const char*>(Vtlo);

    auto issue = [&](int kt, int st) {
        uint32_t s0a = smem_base + st * FSTAGE;
#pragma unroll
        for (int i = 0; i < 2; i++) {
            size_t gk = 2 * (((size_t)bh * SEQ + kt * 64 + cr[i]) * DK + cc[i] * 8);
            CP_ASYNC16(s0a + sdst[i],            pKhi + gk);
            CP_ASYNC16(s0a + FARR + sdst[i],     pKlo + gk);
            size_t gv = 2 * (((size_t)bh * DK + cr[i]) * SEQ + kt * 64 + cc[i] * 8);
            CP_ASYNC16(s0a + 2 * FARR + sdst[i], pVhi + gv);
            CP_ASYNC16(s0a + 3 * FARR + sdst[i], pVlo + gv);
        }
        CP_COMMIT();
    };

    const int ktmax = 2 * qb + 1;
    issue(0, 0);

    for (int kt = 0; kt <= ktmax; kt++) {
        const int st = kt & 1;
        if (kt < ktmax) { issue(kt + 1, st ^ 1); CP_WAIT1(); }
        else            { CP_WAIT0(); }
        __syncthreads();

        const int kg0 = kt * 64;
        if (kg0 <= q0 + 15) {
            const uint32_t* uKhi = reinterpret_cast<const uint32_t*>(smem + st * FSTAGE);
            const uint32_t* uKlo = reinterpret_cast<const uint32_t*>(smem + st * FSTAGE + FARR);
            const uint32_t* uVhi = reinterpret_cast<const uint32_t*>(smem + st * FSTAGE + 2 * FARR);
            const uint32_t* uVlo = reinterpret_cast<const uint32_t*>(smem + st * FSTAGE + 3 * FARR);

            float sacc[8][4];
#pragma unroll
            for (int nf = 0; nf < 8; nf++)
#pragma unroll
                for (int e = 0; e < 4; e++) sacc[nf][e] = 0.f;

#pragma unroll
            for (int ks = 0; ks < 4; ks++) {
#pragma unroll
                for (int nf = 0; nf < 8; nf++) {
                    int w = (nf * 8 + gr) * 36 + ks * 8 + gc;
                    uint32_t b0 = uKhi[w], b1 = uKhi[w + 4];
                    uint32_t c0 = uKlo[w], c1 = uKlo[w + 4];
                    mma16816(sacc[nf], qfh[ks][0], qfh[ks][1], qfh[ks][2], qfh[ks][3], b0, b1);
                    mma16816(sacc[nf], qfh[ks][0], qfh[ks][1], qfh[ks][2], qfh[ks][3], c0, c1);
                    mma16816(sacc[nf], qfl[ks][0], qfl[ks][1], qfl[ks][2], qfl[ks][3], b0, b1);
                }
            }

            if (kg0 + 63 > q0) {
#pragma unroll
                for (int nf = 0; nf < 8; nf++) {
                    int key = kg0 + nf * 8 + gc * 2;
                    int r0 = q0 + gr, r1 = r0 + 8;
                    if (key > r0)     sacc[nf][0] = -INFINITY;
                    if (key + 1 > r0) sacc[nf][1] = -INFINITY;
                    if (key > r1)     sacc[nf][2] = -INFINITY;
                    if (key + 1 > r1) sacc[nf][3] = -INFINITY;
                }
            }

            float mx0 = -INFINITY, mx1 = -INFINITY;
#pragma unroll
            for (int nf = 0; nf < 8; nf++) {
                mx0 = fmaxf(mx0, fmaxf(sacc[nf][0], sacc[nf][1]));
                mx1 = fmaxf(mx1, fmaxf(sacc[nf][2], sacc[nf][3]));
            }
            mx0 = fmaxf(mx0, __shfl_xor_sync(0xffffffffu, mx0, 1));
            mx0 = fmaxf(mx0, __shfl_xor_sync(0xffffffffu, mx0, 2));
            mx1 = fmaxf(mx1, __shfl_xor_sync(0xffffffffu, mx1, 1));
            mx1 = fmaxf(mx1, __shfl_xor_sync(0xffffffffu, mx1, 2));

            float mn0 = fmaxf(m0, mx0), mn1 = fmaxf(m1, mx1);
            float f0 = __expf(m0 - mn0), f1 = __expf(m1 - mn1);
            m0 = mn0; m1 = mn1;

            float sum0 = 0.f, sum1 = 0.f;
#pragma unroll
            for (int nf = 0; nf < 8; nf++) {
                sacc[nf][0] = __expf(sacc[nf][0] - mn0);
                sacc[nf][1] = __expf(sacc[nf][1] - mn0);
                sacc[nf][2] = __expf(sacc[nf][2] - mn1);
                sacc[nf][3] = __expf(sacc[nf][3] - mn1);
                sum0 += sacc[nf][0] + sacc[nf][1];
                sum1 += sacc[nf][2] + sacc[nf][3];
            }
            sum0 += __shfl_xor_sync(0xffffffffu, sum0, 1);
            sum0 += __shfl_xor_sync(0xffffffffu, sum0, 2);
            sum1 += __shfl_xor_sync(0xffffffffu, sum1, 1);
            sum1 += __shfl_xor_sync(0xffffffffu, sum1, 2);
            l0 = l0 * f0 + sum0;
            l1 = l1 * f1 + sum1;

#pragma unroll
            for (int nf = 0; nf < 8; nf++) {
                accO[nf][0] *= f0; accO[nf][1] *= f0;
                accO[nf][2] *= f1; accO[nf][3] *= f1;
            }

            uint32_t pah[4][4], pal[4][4];
#pragma unroll
            for (int j = 0; j < 4; j++) {
                float p00 = sacc[2 * j][0],     p01 = sacc[2 * j][1];
                float p02 = sacc[2 * j][2],     p03 = sacc[2 * j][3];
                float p10 = sacc[2 * j + 1][0], p11 = sacc[2 * j + 1][1];
                float p12 = sacc[2 * j + 1][2], p13 = sacc[2 * j + 1][3];
                pah[j][0] = packbf2(p00, p01);
                pah[j][1] = packbf2(p02, p03);
                pah[j][2] = packbf2(p10, p11);
                pah[j][3] = packbf2(p12, p13);
                pal[j][0] = packbf2(p00 - __bfloat162float(__float2bfloat16(p00)),
                                    p01 - __bfloat162float(__float2bfloat16(p01)));
                pal[j][1] = packbf2(p02 - __bfloat162float(__float2bfloat16(p02)),
                                    p03 - __bfloat162float(__float2bfloat16(p03)));
                pal[j][2] = packbf2(p10 - __bfloat162float(__float2bfloat16(p10)),
                                    p11 - __bfloat162float(__float2bfloat16(p11)));
                pal[j][3] = packbf2(p12 - __bfloat162float(__float2bfloat16(p12)),
                                    p13 - __bfloat162float(__float2bfloat16(p13)));
            }

#pragma unroll
            for (int ks = 0; ks < 4; ks++) {
#pragma unroll
                for (int nf = 0; nf < 8; nf++) {
                    int w = (nf * 8 + gr) * 36 + ks * 8 + gc;
                    uint32_t v0 = uVhi[w], v1 = uVhi[w + 4];
                    uint32_t u0 = uVlo[w], u1 = uVlo[w + 4];
                    mma16816(accO[nf], pah[ks][0], pah[ks][1], pah[ks][2], pah[ks][3], v0, v1);
                    mma16816(accO[nf], pah[ks][0], pah[ks][1], pah[ks][2], pah[ks][3], u0, u1);
                    mma16816(accO[nf], pal[ks][0], pal[ks][1], pal[ks][2], pal[ks][3], v0, v1);
                }
            }
        }
        __syncthreads();
    }

    const int b = bh >> 4;
    const int h = bh & 15;
    const float inv0 = 1.0f / l0, inv1 = 1.0f / l1;
    const int r0 = q0 + gr, r1 = r0 + 8;
#pragma unroll
    for (int nf = 0; nf < 8; nf++) {
        int col = h * DK + nf * 8 + gc * 2;
        size_t o0 = ((size_t)(b * SEQ) + r0) * DMODEL + col;
        size_t o1 = ((size_t)(b * SEQ) + r1) * DMODEL + col;
        float v00 = accO[nf][0] * inv0, v01 = accO[nf][1] * inv0;
        float v10 = accO[nf][2] * inv1, v11 = accO[nf][3] * inv1;
        *reinterpret_cast<uint32_t*>(&Ohi[o0]) = packbf2(v00, v01);
        *reinterpret_cast<uint32_t*>(&Ohi[o1]) = packbf2(v10, v11);
        *reinterpret_cast<uint32_t*>(&Olo[o0]) =
            packbf2(v00 - __bfloat162float(__float2bfloat16(v00)),
                    v01 - __bfloat162float(__float2bfloat16(v01)));
        *reinterpret_cast<uint32_t*>(&Olo[o1]) =
            packbf2(v10 - __bfloat162float(__float2bfloat16(v10)),
                    v11 - __bfloat162float(__float2bfloat16(v11)));
    }
}

// ---------------------------------------------------------------------------
extern "C" void kernel_launch(void* const* d_in, const int* in_sizes, int n_in,
                              void* d_out, int out_size)
{
    const float* q    = (const float*)d_in[0];
    const float* k    = (const float*)d_in[1];
    const float* v    = (const float*)d_in[2];
    const float* W_Aq = (const float*)d_in[4];
    const float* W_Ak = (const float*)d_in[5];
    const float* W_Av = (const float*)d_in[6];
    const float* W_Bq = (const float*)d_in[7];
    const float* W_Bk = (const float*)d_in[8];
    const float* W_Bv = (const float*)d_in[9];
    const float* Wo   = (const float*)d_in[10];
    float* out = (float*)d_out;

    float* scratch = nullptr;
    cudaGetSymbolAddress((void**)&scratch, g_scratch);
    __nv_bfloat16* bs = nullptr;
    cudaGetSymbolAddress((void**)&bs, g_bf);

    float* sAq = scratch + OFF_AQ;
    float* sAk = scratch + OFF_AK;
    float* sAv = scratch + OFF_AV;
    float* sBq = scratch + OFF_BQ;
    float* sBk = scratch + OFF_BK;
    float* sBv = scratch + OFF_BV;

    const int GEMSMEM = 2 * GSTAGE;         // 147456
    const int FLSMEM  = 2 * FSTAGE;         // 73728
    cudaFuncSetAttribute(tc_gemm_kernel,
                         cudaFuncAttributeMaxDynamicSharedMemorySize, GEMSMEM);
    cudaFuncSetAttribute(flash_mma_kernel,
                         cudaFuncAttributeMaxDynamicSharedMemorySize, FLSMEM);

    const int MY = NTOK / 128;   // 32

    // 0) rope table + input splits + weight transpose-splits
    rope_table_kernel<<<(SEQ * 32 + 255) / 256, 256>>>();
    split3_kernel<<<dim3((TOKD + 255) / 256, 1, 3), 256>>>(
        q, k, v, bs + BOFF_QHI, bs + BOFF_QLO, bs + BOFF_KHI, bs + BOFF_KLO,
        bs + BOFF_VHI, bs + BOFF_VLO, TOKD);

    TsCfg7 ts;
    ts.c[0] = { W_Bq, bs + BOFF_WBQ_HI, bs + BOFF_WBQ_LO, 384, 384 };
    ts.c[1] = { W_Bk, bs + BOFF_WBK_HI, bs + BOFF_WBK_LO, 128, 128 };
    ts.c[2] = { W_Bv, bs + BOFF_WBV_HI, bs + BOFF_WBV_LO, 128, 128 };
    ts.c[3] = { Wo,   bs + BOFF_WO_HI,  bs + BOFF_WO_LO,  1024, 1024 };
    ts.c[4] = { W_Aq, bs + BOFF_WAQ_HI, bs + BOFF_WAQ_LO, 96, 128 };
    ts.c[5] = { W_Ak, bs + BOFF_WAK_HI, bs + BOFF_WAK_LO, 32, 128 };
    ts.c[6] = { W_Av, bs + BOFF_WAV_HI, bs + BOFF_WAV_LO, 32, 128 };
    tsplit7_kernel<<<dim3(32, 32, 7), dim3(32, 8)>>>(ts);

    // 1) all 6 projections in one pipelined HMMA launch (512 threads)
    GemmCfg6 gp;
    gp.c[0] = { bs + BOFF_QHI, bs + BOFF_QLO, bs + BOFF_WBQ_HI, bs + BOFF_WBQ_LO, sBq, 384, 384 };
    gp.c[1] = { bs + BOFF_KHI, bs + BOFF_KLO, bs + BOFF_WBK_HI, bs + BOFF_WBK_LO, sBk, 128, 128 };
    gp.c[2] = { bs + BOFF_VHI, bs + BOFF_VLO, bs + BOFF_WBV_HI, bs + BOFF_WBV_LO, sBv, 128, 128 };
    gp.c[3] = { bs + BOFF_QHI, bs + BOFF_QLO, bs + BOFF_WAQ_HI, bs + BOFF_WAQ_LO, sAq, 96, 128 };
    gp.c[4] = { bs + BOFF_KHI, bs + BOFF_KLO, bs + BOFF_WAK_HI, bs + BOFF_WAK_LO, sAk, 32, 128 };
    gp.c[5] = { bs + BOFF_VHI, bs + BOFF_VLO, bs + BOFF_WAV_HI, bs + BOFF_WAV_LO, sAv, 32, 128 };
    tc_gemm_kernel<<<dim3(3, MY, 6), 512, GEMSMEM>>>(gp);

    // 2) fused RoPE + contraction (q & k) and V contraction+transpose
    {
        int total = NTOK * HEADS * DK;
        contract_rope2_kernel<<<dim3((total + 255) / 256, 1, 2), 256>>>(
            sAq, sBq, bs + BOFF_FQHI, bs + BOFF_FQLO,
            sAk, sBk, bs + BOFF_FKHI, bs + BOFF_FKLO);
        fvt_kernel<<<dim3(SEQ / 32, DK / 32, BH), dim3(32, 8)>>>(
            sAv, sBv, bs + BOFF_FVTHI, bs + BOFF_FVTLO);
    }

    // 3) HMMA causal flash attention (FQ=128, 2 CTAs/SM)
    flash_mma_kernel<<<dim3(SEQ / 128, BH), 256, FLSMEM>>>(
        bs + BOFF_FQHI, bs + BOFF_FQLO, bs + BOFF_FKHI, bs + BOFF_FKLO,
        bs + BOFF_FVTHI, bs + BOFF_FVTLO, bs + BOFF_OAHI, bs + BOFF_OALO);

    // 4) output projection (512 threads)
    GemmCfg6 go;
    go.c[0] = { bs + BOFF_OAHI, bs + BOFF_OALO, bs + BOFF_WO_HI, bs + BOFF_WO_LO, out, 1024, 1024 };
    go.c[1] = go.c[0]; go.c[2] = go.c[0]; go.c[3] = go.c[0]; go.c[4] = go.c[0]; go.c[5] = go.c[0];
    tc_gemm_kernel<<<dim3(8, MY, 1), 512, GEMSMEM>>>(go);
}